// round 8
// baseline (speedup 1.0000x reference)
#include <cuda_runtime.h>
#include <stdint.h>

#define NUM_CLASSES 20
#define B    8
#define NV   5
#define CH   3
#define HH   120
#define WW   160
#define HW   (HH*WW)        // 19200
#define NPIX (NV*HW)        // 96000
#define PP   131072
#define KNN  3

// Channel-last packed image: one float4 per (b, v*h*w + pix). 12.3 MB.
__device__ float4 g_packed[B * NPIX];

// ---------------------------------------------------------------------------
// Kernel 1: pack images [b, nv, c, h, w] -> float4[b*NPIX] (channel-last).
// Each thread transposes 4 consecutive pixels (3x LDG.128 in, 4x STG.128 out).
// ---------------------------------------------------------------------------
__global__ void pack_kernel(const float* __restrict__ images) {
    int i = blockIdx.x * blockDim.x + threadIdx.x;   // 0 .. B*NPIX/4-1
    if (i >= B * NPIX / 4) return;
    int pix4 = i * 4;
    int b    = pix4 / NPIX;
    int r    = pix4 - b * NPIX;
    int v    = r / HW;
    int pix  = r - v * HW;                            // multiple of 4

    const float* base = images + ((size_t)(b * NV + v) * CH) * HW + pix;
    float4 c0 = *reinterpret_cast<const float4*>(base);
    float4 c1 = *reinterpret_cast<const float4*>(base + HW);
    float4 c2 = *reinterpret_cast<const float4*>(base + 2 * HW);

    float4* dst = g_packed + pix4;
    dst[0] = make_float4(c0.x, c1.x, c2.x, 0.0f);
    dst[1] = make_float4(c0.y, c1.y, c2.y, 0.0f);
    dst[2] = make_float4(c0.z, c1.z, c2.z, 0.0f);
    dst[3] = make_float4(c0.w, c1.w, c2.w, 0.0f);
}

// ---------------------------------------------------------------------------
// Kernel 2: 2 points per thread. Gather 6 neighbors (float4), mean per point,
// 20x3 matvec with weights packed as float4(w0,w1,w2,bias) per class so the
// per-class shared read is ONE LDS.128 broadcast (was 4 scalar LDS -> cut
// L1 wavefronts ~19%). Streaming float2 stores.
// ---------------------------------------------------------------------------
__global__ void gather_matvec_kernel(const int* __restrict__ knn,
                                     const float* __restrict__ W2d,
                                     const float* __restrict__ b2d,
                                     float* __restrict__ out) {
    __shared__ float4 sWB[NUM_CLASSES];   // (w0, w1, w2, bias)
    {
        int t = threadIdx.x;
        if (t < NUM_CLASSES)
            sWB[t] = make_float4(W2d[t * 3 + 0], W2d[t * 3 + 1],
                                 W2d[t * 3 + 2], b2d[t]);
    }
    __syncthreads();

    const int PPT = 2;                                   // points per thread
    int gid = blockIdx.x * blockDim.x + threadIdx.x;     // 0 .. B*PP/2-1
    int b   = gid / (PP / PPT);
    int p0  = (gid - b * (PP / PPT)) * PPT;

    // 6 contiguous int32 indices; byte offset = (b*PP+p0)*12 = mult of 24 ->
    // 8B-aligned, read as 3x int2.
    const int2* ip = reinterpret_cast<const int2*>(
        knn + ((size_t)b * PP + p0) * KNN);
    int2 i0 = ip[0], i1 = ip[1], i2 = ip[2];
    int idx[6] = { i0.x, i0.y, i1.x, i1.y, i2.x, i2.y };
    #pragma unroll
    for (int j = 0; j < 6; j++) {
        int v = idx[j];
        v = v < 0 ? 0 : v;
        v = v >= NPIX ? NPIX - 1 : v;
        idx[j] = v;
    }

    const float4* pk = g_packed + b * NPIX;
    float4 g[6];
    #pragma unroll
    for (int j = 0; j < 6; j++) g[j] = __ldg(&pk[idx[j]]);

    const float inv3 = 1.0f / 3.0f;
    float mx0 = (g[0].x + g[1].x + g[2].x) * inv3;
    float my0 = (g[0].y + g[1].y + g[2].y) * inv3;
    float mz0 = (g[0].z + g[1].z + g[2].z) * inv3;
    float mx1 = (g[3].x + g[4].x + g[5].x) * inv3;
    float my1 = (g[3].y + g[4].y + g[5].y) * inv3;
    float mz1 = (g[3].z + g[4].z + g[5].z) * inv3;

    float* ob = out + (size_t)b * NUM_CLASSES * PP + p0;
    #pragma unroll
    for (int o = 0; o < NUM_CLASSES; o++) {
        float4 w = sWB[o];                 // one LDS.128 broadcast
        float2 r;
        r.x = w.w + w.x * mx0 + w.y * my0 + w.z * mz0;
        r.y = w.w + w.x * mx1 + w.y * my1 + w.z * mz1;
        __stcs(reinterpret_cast<float2*>(ob + (size_t)o * PP), r);
    }
}

// ---------------------------------------------------------------------------
extern "C" void kernel_launch(void* const* d_in, const int* in_sizes, int n_in,
                              void* d_out, int out_size) {
    const float* images = (const float*)d_in[0];  // [8,5,3,120,160] f32
    const int*   knn    = (const int*)d_in[1];    // [8,131072,3] int32
    const float* W2d    = (const float*)d_in[2];  // [20,3]
    const float* b2d    = (const float*)d_in[3];  // [20]
    float*       out    = (float*)d_out;          // [8,20,131072] f32

    (void)in_sizes; (void)n_in; (void)out_size;

    {
        int n = B * NPIX / 4;             // 192000
        int threads = 256;
        int blocks = (n + threads - 1) / threads;
        pack_kernel<<<blocks, threads>>>(images);
    }
    {
        int n = B * PP / 2;               // 524288 threads
        int threads = 256;
        int blocks = n / threads;         // 2048
        gather_matvec_kernel<<<blocks, threads>>>(knn, W2d, b2d, out);
    }
}

// round 10
// speedup vs baseline: 1.0010x; 1.0010x over previous
#include <cuda_runtime.h>
#include <stdint.h>

#define NUM_CLASSES 20
#define B    8
#define NV   5
#define CH   3
#define HH   120
#define WW   160
#define HW   (HH*WW)        // 19200
#define NPIX (NV*HW)        // 96000
#define PP   131072
#define KNN  3

// Channel-last packed image: one float4 per (b, v*h*w + pix). 12.3 MB.
__device__ float4 g_packed[B * NPIX];

// ---------------------------------------------------------------------------
// Kernel 1: pack images [b, nv, c, h, w] -> float4[b*NPIX] (channel-last).
// Each thread transposes 4 consecutive pixels (3x LDG.128 in, 4x STG.128 out).
// ---------------------------------------------------------------------------
__global__ void pack_kernel(const float* __restrict__ images) {
    int i = blockIdx.x * blockDim.x + threadIdx.x;   // 0 .. B*NPIX/4-1
    if (i >= B * NPIX / 4) return;
    int pix4 = i * 4;
    int b    = pix4 / NPIX;
    int r    = pix4 - b * NPIX;
    int v    = r / HW;
    int pix  = r - v * HW;                            // multiple of 4

    const float* base = images + ((size_t)(b * NV + v) * CH) * HW + pix;
    float4 c0 = *reinterpret_cast<const float4*>(base);
    float4 c1 = *reinterpret_cast<const float4*>(base + HW);
    float4 c2 = *reinterpret_cast<const float4*>(base + 2 * HW);

    float4* dst = g_packed + pix4;
    dst[0] = make_float4(c0.x, c1.x, c2.x, 0.0f);
    dst[1] = make_float4(c0.y, c1.y, c2.y, 0.0f);
    dst[2] = make_float4(c0.z, c1.z, c2.z, 0.0f);
    dst[3] = make_float4(c0.w, c1.w, c2.w, 0.0f);
}

// ---------------------------------------------------------------------------
// Kernel 2: 2 points per thread. Gather 6 neighbors (float4), mean per point,
// 20x3 matvec with weights packed as float4(w0,w1,w2,bias) per class so the
// per-class shared read is ONE LDS.128 broadcast (was 4 scalar LDS -> cut
// L1 wavefronts ~19%). Streaming float2 stores.
// ---------------------------------------------------------------------------
__global__ void gather_matvec_kernel(const int* __restrict__ knn,
                                     const float* __restrict__ W2d,
                                     const float* __restrict__ b2d,
                                     float* __restrict__ out) {
    __shared__ float4 sWB[NUM_CLASSES];   // (w0, w1, w2, bias)
    {
        int t = threadIdx.x;
        if (t < NUM_CLASSES)
            sWB[t] = make_float4(W2d[t * 3 + 0], W2d[t * 3 + 1],
                                 W2d[t * 3 + 2], b2d[t]);
    }
    __syncthreads();

    const int PPT = 2;                                   // points per thread
    int gid = blockIdx.x * blockDim.x + threadIdx.x;     // 0 .. B*PP/2-1
    int b   = gid / (PP / PPT);
    int p0  = (gid - b * (PP / PPT)) * PPT;

    // 6 contiguous int32 indices; byte offset = (b*PP+p0)*12 = mult of 24 ->
    // 8B-aligned, read as 3x int2.
    const int2* ip = reinterpret_cast<const int2*>(
        knn + ((size_t)b * PP + p0) * KNN);
    int2 i0 = ip[0], i1 = ip[1], i2 = ip[2];
    int idx[6] = { i0.x, i0.y, i1.x, i1.y, i2.x, i2.y };
    #pragma unroll
    for (int j = 0; j < 6; j++) {
        int v = idx[j];
        v = v < 0 ? 0 : v;
        v = v >= NPIX ? NPIX - 1 : v;
        idx[j] = v;
    }

    const float4* pk = g_packed + b * NPIX;
    float4 g[6];
    #pragma unroll
    for (int j = 0; j < 6; j++) g[j] = __ldg(&pk[idx[j]]);

    const float inv3 = 1.0f / 3.0f;
    float mx0 = (g[0].x + g[1].x + g[2].x) * inv3;
    float my0 = (g[0].y + g[1].y + g[2].y) * inv3;
    float mz0 = (g[0].z + g[1].z + g[2].z) * inv3;
    float mx1 = (g[3].x + g[4].x + g[5].x) * inv3;
    float my1 = (g[3].y + g[4].y + g[5].y) * inv3;
    float mz1 = (g[3].z + g[4].z + g[5].z) * inv3;

    float* ob = out + (size_t)b * NUM_CLASSES * PP + p0;
    #pragma unroll
    for (int o = 0; o < NUM_CLASSES; o++) {
        float4 w = sWB[o];                 // one LDS.128 broadcast
        float2 r;
        r.x = w.w + w.x * mx0 + w.y * my0 + w.z * mz0;
        r.y = w.w + w.x * mx1 + w.y * my1 + w.z * mz1;
        __stcs(reinterpret_cast<float2*>(ob + (size_t)o * PP), r);
    }
}

// ---------------------------------------------------------------------------
extern "C" void kernel_launch(void* const* d_in, const int* in_sizes, int n_in,
                              void* d_out, int out_size) {
    const float* images = (const float*)d_in[0];  // [8,5,3,120,160] f32
    const int*   knn    = (const int*)d_in[1];    // [8,131072,3] int32
    const float* W2d    = (const float*)d_in[2];  // [20,3]
    const float* b2d    = (const float*)d_in[3];  // [20]
    float*       out    = (float*)d_out;          // [8,20,131072] f32

    (void)in_sizes; (void)n_in; (void)out_size;

    {
        int n = B * NPIX / 4;             // 192000
        int threads = 256;
        int blocks = (n + threads - 1) / threads;
        pack_kernel<<<blocks, threads>>>(images);
    }
    {
        int n = B * PP / 2;               // 524288 threads
        int threads = 256;
        int blocks = n / threads;         // 2048
        gather_matvec_kernel<<<blocks, threads>>>(knn, W2d, b2d, out);
    }
}